// round 7
// baseline (speedup 1.0000x reference)
#include <cuda_runtime.h>

#define EMB 512
#define ROW 1024           // 2*EMB floats per head/tail row
#define WPB 8              // warps (rows) per block
#define THREADS (WPB * 32)

__global__ __launch_bounds__(THREADS, 4)
void interht_kernel(const float* __restrict__ head,
                    const float* __restrict__ tail,
                    const float* __restrict__ rel_emb,
                    const int*   __restrict__ rel_id,
                    float*       __restrict__ out,
                    int batch)
{
    const int lane = threadIdx.x & 31;
    const int warp = threadIdx.x >> 5;
    const int row  = blockIdx.x * WPB + warp;
    if (row >= batch) return;

    const float4* h4 = reinterpret_cast<const float4*>(head + (size_t)row * ROW);
    const float4* t4 = reinterpret_cast<const float4*>(tail + (size_t)row * ROW);
    const int rid = __ldg(rel_id + row);
    const float4* r4 = reinterpret_cast<const float4*>(rel_emb + (size_t)rid * EMB);

    // 17 raw moments (single streaming pass; nothing held across a reduction)
    float a0 = 0.f, a1 = 0.f, a2 = 0.f, a3 = 0.f;          // |hm|^2 |ha|^2 |tm|^2 |ta|^2
    float a4 = 0.f, a5 = 0.f, a6 = 0.f;                    // (hm ta)^2, (hm ta)hm, (hm ta)r
    float a7 = 0.f, a8 = 0.f, a9 = 0.f;                    // (tm ha)^2, (tm ha)tm, (tm ha)r
    float a10 = 0.f, a11 = 0.f, a12 = 0.f;                 // (hm ta)(tm ha), (hm ta)tm, (tm ha)hm
    float a13 = 0.f, a14 = 0.f, a15 = 0.f, a16 = 0.f;      // hm tm, hm r, tm r, r^2

#define ACC(HM, HA, TM, TA, RV)                                     \
    do {                                                            \
        const float pm = (HM) * (TA);                               \
        const float pw = (TM) * (HA);                               \
        a0  = fmaf((HM), (HM), a0);                                 \
        a1  = fmaf((HA), (HA), a1);                                 \
        a2  = fmaf((TM), (TM), a2);                                 \
        a3  = fmaf((TA), (TA), a3);                                 \
        a4  = fmaf(pm, pm, a4);                                     \
        a5  = fmaf(pm, (HM), a5);                                   \
        a6  = fmaf(pm, (RV), a6);                                   \
        a7  = fmaf(pw, pw, a7);                                     \
        a8  = fmaf(pw, (TM), a8);                                   \
        a9  = fmaf(pw, (RV), a9);                                   \
        a10 = fmaf(pm, pw, a10);                                    \
        a11 = fmaf(pm, (TM), a11);                                  \
        a12 = fmaf(pw, (HM), a12);                                  \
        a13 = fmaf((HM), (TM), a13);                                \
        a14 = fmaf((HM), (RV), a14);                                \
        a15 = fmaf((TM), (RV), a15);                                \
        a16 = fmaf((RV), (RV), a16);                                \
    } while (0)

    #pragma unroll
    for (int i = 0; i < 4; i++) {
        const float4 HM = __ldcs(h4 + lane + 32 * i);
        const float4 HA = __ldcs(h4 + 128 + lane + 32 * i);
        const float4 TM = __ldcs(t4 + lane + 32 * i);
        const float4 TA = __ldcs(t4 + 128 + lane + 32 * i);
        const float4 RV = __ldg(r4 + lane + 32 * i);
        ACC(HM.x, HA.x, TM.x, TA.x, RV.x);
        ACC(HM.y, HA.y, TM.y, TA.y, RV.y);
        ACC(HM.z, HA.z, TM.z, TA.z, RV.z);
        ACC(HM.w, HA.w, TM.w, TA.w, RV.w);
    }
#undef ACC

    // Warp-wide reduction of all 17 moments (shuffle butterflies only)
    #pragma unroll
    for (int o = 16; o > 0; o >>= 1) {
        a0  += __shfl_xor_sync(0xffffffffu, a0, o);
        a1  += __shfl_xor_sync(0xffffffffu, a1, o);
        a2  += __shfl_xor_sync(0xffffffffu, a2, o);
        a3  += __shfl_xor_sync(0xffffffffu, a3, o);
        a4  += __shfl_xor_sync(0xffffffffu, a4, o);
        a5  += __shfl_xor_sync(0xffffffffu, a5, o);
        a6  += __shfl_xor_sync(0xffffffffu, a6, o);
        a7  += __shfl_xor_sync(0xffffffffu, a7, o);
        a8  += __shfl_xor_sync(0xffffffffu, a8, o);
        a9  += __shfl_xor_sync(0xffffffffu, a9, o);
        a10 += __shfl_xor_sync(0xffffffffu, a10, o);
        a11 += __shfl_xor_sync(0xffffffffu, a11, o);
        a12 += __shfl_xor_sync(0xffffffffu, a12, o);
        a13 += __shfl_xor_sync(0xffffffffu, a13, o);
        a14 += __shfl_xor_sync(0xffffffffu, a14, o);
        a15 += __shfl_xor_sync(0xffffffffu, a15, o);
        a16 += __shfl_xor_sync(0xffffffffu, a16, o);
    }

    if (lane == 0) {
        // inv norms: p=hm, q=ha, s=tm, t=ta (matching reference eps clamp)
        const float p = 1.0f / fmaxf(sqrtf(a0), 1e-12f);
        const float q = 1.0f / fmaxf(sqrtf(a1), 1e-12f);
        const float s = 1.0f / fmaxf(sqrtf(a2), 1e-12f);
        const float t = 1.0f / fmaxf(sqrtf(a3), 1e-12f);

        // |d|^2 with d = u*x + u + r - w*v - w (elementwise; u=hm*p, v=ha*q, w=tm*s, x=ta*t)
        const float dd =
              a4 * (p * p) * (t * t)          // |u x|^2
            + a0 * (p * p)                    // |u|^2 (=1)
            + a16                             // |r|^2
            + a7 * (s * s) * (q * q)          // |w v|^2
            + a2 * (s * s)                    // |w|^2 (=1)
            + 2.0f * ( a5 * (p * p) * t       // (ux).u
                     + a6 * (p * t)           // (ux).r
                     + a14 * p                // u.r
                     + a8 * (s * s) * q )     // (wv).w
            - 2.0f * ( a10 * (p * t * s * q)  // (ux).(wv)
                     + a11 * (p * t * s)      // (ux).w
                     + a12 * (p * s * q)      // u.(wv)
                     + a13 * (p * s)          // u.w
                     + a9  * (s * q)          // r.(wv)
                     + a15 * s );             // r.w

        out[row] = -sqrtf(dd);
    }
}

extern "C" void kernel_launch(void* const* d_in, const int* in_sizes, int n_in,
                              void* d_out, int out_size)
{
    const float* head    = (const float*)d_in[0];
    const float* tail    = (const float*)d_in[1];
    const float* rel_emb = (const float*)d_in[2];
    const int*   rel_id  = (const int*)d_in[3];
    float*       out     = (float*)d_out;

    const int batch = out_size;                    // 131072 rows
    const int grid  = (batch + WPB - 1) / WPB;
    interht_kernel<<<grid, THREADS>>>(head, tail, rel_emb, rel_id, out, batch);
}